// round 5
// baseline (speedup 1.0000x reference)
#include <cuda_runtime.h>
#include <cuda_bf16.h>
#include <cstdint>

// ---------------------------------------------------------------------------
// Problem constants
// ---------------------------------------------------------------------------
#define BATCH   4
#define SEQ     4096
#define DMODEL  1024
#define NHEADS  8
#define HDIM    64
#define STATE   512            // NHEADS*HDIM
#define PROJW   2048           // 4*STATE
#define ROWS    (BATCH*SEQ)    // 16384

// GEMM tiling
#define BM 128
#define BN 256
#define NSTAGE 4
#define A_STRIDE 20            // words per A row (16 + pad)
#define B_STRIDE 20            // words per B row
#define A_STAGE_W (BM * A_STRIDE)   // 2560 words
#define B_STAGE_W (BN * B_STRIDE)   // 5120 words
#define SMEM_DYN_BYTES (NSTAGE * (A_STAGE_W + B_STAGE_W) * 4)  // 122880

// ---------------------------------------------------------------------------
// Scratch (device globals -- no runtime allocation allowed)
// ---------------------------------------------------------------------------
__device__ float g_proj[(size_t)ROWS * PROJW];   // [xi_raw | xf | xr | g]
__device__ float g_xi  [(size_t)ROWS * STATE];   // conv+silu output
__device__ float g_y   [(size_t)ROWS * STATE];   // recurrence output
__device__ float g_yn  [(size_t)ROWS * STATE];   // gated+normed (tf32, permuted)
__device__ float g_xt  [(size_t)ROWS * DMODEL];  // x  (tf32-rounded, k-permuted)
__device__ float g_wint[(size_t)PROJW * DMODEL]; // w_in  (tf32, k-permuted)
__device__ float g_woutt[(size_t)DMODEL * STATE];// w_out (tf32, k-permuted)

// ---------------------------------------------------------------------------
// Helpers
// ---------------------------------------------------------------------------
__device__ __forceinline__ unsigned long long pk2(float lo, float hi) {
    unsigned long long r;
    asm("mov.b64 %0, {%1, %2};" : "=l"(r) : "f"(lo), "f"(hi));
    return r;
}
__device__ __forceinline__ void fma2(unsigned long long& d,
                                     unsigned long long a,
                                     unsigned long long b) {
    asm("fma.rn.f32x2 %0, %1, %2, %0;" : "+l"(d) : "l"(a), "l"(b));
}
__device__ __forceinline__ unsigned long long add2(unsigned long long a,
                                                   unsigned long long b) {
    unsigned long long d;
    asm("add.rn.f32x2 %0, %1, %2;" : "=l"(d) : "l"(a), "l"(b));
    return d;
}
__device__ __forceinline__ float hadd2(unsigned long long v) {
    float a, b;
    asm("mov.b64 {%0, %1}, %2;" : "=f"(a), "=f"(b) : "l"(v));
    return a + b;
}
__device__ __forceinline__ float fsigmoid(float x) {
    return __fdividef(1.0f, 1.0f + __expf(-x));
}
__device__ __forceinline__ float ftanh(float x) {
    float e = __expf(2.0f * x);
    return 1.0f - __fdividef(2.0f, e + 1.0f);
}
__device__ __forceinline__ uint32_t f2tf(float f) {
    uint32_t u;
    asm("cvt.rna.tf32.f32 %0, %1;" : "=r"(u) : "f"(f));
    return u;
}
__device__ __forceinline__ void mma_tf32(float* c, const uint32_t* a,
                                         const uint32_t* b) {
    asm volatile(
        "mma.sync.aligned.m16n8k8.row.col.f32.tf32.tf32.f32 "
        "{%0,%1,%2,%3}, {%4,%5,%6,%7}, {%8,%9}, {%0,%1,%2,%3};\n"
        : "+f"(c[0]), "+f"(c[1]), "+f"(c[2]), "+f"(c[3])
        : "r"(a[0]), "r"(a[1]), "r"(a[2]), "r"(a[3]), "r"(b[0]), "r"(b[1]));
}
__device__ __forceinline__ void cp16(uint32_t dst, const float* src) {
    asm volatile("cp.async.cg.shared.global [%0], [%1], 16;\n"
                 :: "r"(dst), "l"(src));
}

// ---------------------------------------------------------------------------
// Pre-pass: tf32-round (rna) + permute k within groups of 8: out position
// order (k=0,4,1,5,2,6,3,7).  Applied identically to A and B of every GEMM,
// so results are bit-identical to cvt-per-fragment.
// ---------------------------------------------------------------------------
__global__ void __launch_bounds__(256)
round_permute(const float* __restrict__ src, float* __restrict__ dst,
              int ngroups)
{
    int g = blockIdx.x * 256 + threadIdx.x;
    if (g >= ngroups) return;
    const float4* s = (const float4*)(src + (size_t)g * 8);
    float4 lo = s[0], hi = s[1];    // k = 0..3, 4..7
    float4 o0, o1;
    o0.x = __uint_as_float(f2tf(lo.x));  // k0
    o0.y = __uint_as_float(f2tf(hi.x));  // k4
    o0.z = __uint_as_float(f2tf(lo.y));  // k1
    o0.w = __uint_as_float(f2tf(hi.y));  // k5
    o1.x = __uint_as_float(f2tf(lo.z));  // k2
    o1.y = __uint_as_float(f2tf(hi.z));  // k6
    o1.z = __uint_as_float(f2tf(lo.w));  // k3
    o1.w = __uint_as_float(f2tf(hi.w));  // k7
    float4* d = (float4*)(dst + (size_t)g * 8);
    d[0] = o0; d[1] = o1;
}

// ---------------------------------------------------------------------------
// 128x256 TF32 GEMM body (NT): 256 threads, 8 warps of 64x64, cp.async 4-stage
// Inputs must be tf32-rounded + k-permuted. No cvt in the mainloop.
// ---------------------------------------------------------------------------
__device__ __forceinline__ void gemm_body(const float* __restrict__ Ag0,
                                          const float* __restrict__ Bg0,
                                          float* __restrict__ Cg0,
                                          int K, int ldc)
{
    extern __shared__ float smem_dyn[];
    float* As = smem_dyn;                         // [NSTAGE][BM][A_STRIDE]
    float* Bs = smem_dyn + NSTAGE * A_STAGE_W;    // [NSTAGE][BN][B_STRIDE]
    const uint32_t aBase = (uint32_t)__cvta_generic_to_shared(As);
    const uint32_t bBase = (uint32_t)__cvta_generic_to_shared(Bs);

    const int tid   = threadIdx.x;
    const int lane  = tid & 31;
    const int warp  = tid >> 5;
    const int group = lane >> 2;
    const int tig   = lane & 3;
    const int wm = (warp >> 2) * 64;   // 2 warp rows
    const int wn = (warp & 3) * 64;    // 4 warp cols

    float c[4][8][4];
#pragma unroll
    for (int mt = 0; mt < 4; mt++)
#pragma unroll
        for (int nt = 0; nt < 8; nt++)
#pragma unroll
            for (int q = 0; q < 4; q++) c[mt][nt][q] = 0.0f;

    const int arow0 = tid >> 2;              // 16B chunk mapping
    const int akc   = (tid & 3) << 2;
    const int niter = K >> 4;

    auto load_stage = [&](int st, int ko) {
        const uint32_t aS = aBase + (uint32_t)(st * A_STAGE_W) * 4u;
        const uint32_t bS = bBase + (uint32_t)(st * B_STAGE_W) * 4u;
#pragma unroll
        for (int j = 0; j < 2; j++) {
            int row = arow0 + j * 64;
            cp16(aS + (uint32_t)(row * A_STRIDE + akc) * 4u,
                 Ag0 + (size_t)row * K + ko + akc);
        }
#pragma unroll
        for (int j = 0; j < 4; j++) {
            int row = arow0 + j * 64;
            cp16(bS + (uint32_t)(row * B_STRIDE + akc) * 4u,
                 Bg0 + (size_t)row * K + ko + akc);
        }
        asm volatile("cp.async.commit_group;\n");
    };

    load_stage(0, 0);
    load_stage(1, 16);
    load_stage(2, 32);

    for (int it = 0; it < niter; it++) {
        const int st = it & 3;                // NSTAGE == 4
        asm volatile("cp.async.wait_group 2;\n");
        __syncthreads();

        const float* Ast = As + st * A_STAGE_W;
        const float* Bst = Bs + st * B_STAGE_W;
#pragma unroll
        for (int ks = 0; ks < 2; ks++) {
            const int kp = ks * 8 + 2 * tig;  // permuted pair position
            uint32_t a[4][4], b[8][2];
#pragma unroll
            for (int mt = 0; mt < 4; mt++) {
                const int m = wm + mt * 16 + group;
                float2 u = *(const float2*)&Ast[m * A_STRIDE + kp];
                float2 v = *(const float2*)&Ast[(m + 8) * A_STRIDE + kp];
                a[mt][0] = __float_as_uint(u.x);
                a[mt][1] = __float_as_uint(v.x);
                a[mt][2] = __float_as_uint(u.y);
                a[mt][3] = __float_as_uint(v.y);
            }
#pragma unroll
            for (int nt = 0; nt < 8; nt++) {
                const int n = wn + nt * 8 + group;
                float2 w = *(const float2*)&Bst[n * B_STRIDE + kp];
                b[nt][0] = __float_as_uint(w.x);
                b[nt][1] = __float_as_uint(w.y);
            }
#pragma unroll
            for (int mt = 0; mt < 4; mt++)
#pragma unroll
                for (int nt = 0; nt < 8; nt++)
                    mma_tf32(c[mt][nt], a[mt], b[nt]);
        }

        if (it + 3 < niter)
            load_stage((it + 3) & 3, (it + 3) * 16);
        else
            asm volatile("cp.async.commit_group;\n");  // uniform group count
    }

#pragma unroll
    for (int mt = 0; mt < 4; mt++) {
        const int m0 = wm + mt * 16 + group;
#pragma unroll
        for (int nt = 0; nt < 8; nt++) {
            const int n0 = wn + nt * 8 + 2 * tig;
            *(float2*)(Cg0 + (size_t)m0 * ldc + n0) =
                make_float2(c[mt][nt][0], c[mt][nt][1]);
            *(float2*)(Cg0 + (size_t)(m0 + 8) * ldc + n0) =
                make_float2(c[mt][nt][2], c[mt][nt][3]);
        }
    }
}

__global__ void __launch_bounds__(256)
tf32_gemm_nt(const float* __restrict__ A, const float* __restrict__ B,
             float* __restrict__ C, int K, int ldc)
{
    gemm_body(A + (size_t)blockIdx.y * BM * K,
              B + (size_t)blockIdx.x * BN * K,
              C + (size_t)blockIdx.y * BM * ldc + blockIdx.x * BN,
              K, ldc);
}

// ---------------------------------------------------------------------------
// Sequential recurrence body: 128 threads, one (b,head) per bh.
// ---------------------------------------------------------------------------
__device__ void scan_body(const float* __restrict__ proj,
                          const float* __restrict__ xi_in,
                          const float* __restrict__ sw,
                          float* __restrict__ y, int bh)
{
    const int tid  = threadIdx.x;
    const int k    = tid & 63;
    const bool isf = tid < 64;
    const int head = bh & 7;
    const int b    = bh >> 3;

    __shared__ __align__(16) float h_sh[64];
    __shared__ __align__(16) float hr_sh[64];

    unsigned long long wg[32];  // Wf (f-threads) or Wr (r-threads)
    unsigned long long wz[32];  // W  (f-threads only)
    {
        const int gidx = isf ? (NHEADS + head) : (2 * NHEADS + head);
        const float* base = sw + (size_t)gidx * 64 * 64 + k;
#pragma unroll
        for (int i = 0; i < 32; i++)
            wg[i] = pk2(base[(2 * i) * 64], base[(2 * i + 1) * 64]);
        if (isf) {
            const float* bz = sw + (size_t)head * 64 * 64 + k;
#pragma unroll
            for (int i = 0; i < 32; i++)
                wz[i] = pk2(bz[(2 * i) * 64], bz[(2 * i + 1) * 64]);
        }
    }

    if (tid < 64) h_sh[tid] = 0.0f;
    __syncthreads();

    const float* xg_ptr = proj + (size_t)b * SEQ * PROJW
                          + (isf ? STATE : 2 * STATE) + head * HDIM + k;
    const float* xi_ptr = xi_in + (size_t)b * SEQ * STATE + head * HDIM + k;
    float* y_ptr = y + (size_t)b * SEQ * STATE + head * HDIM + k;

    float xg_buf[4], xi_buf[4];
#pragma unroll
    for (int j = 0; j < 4; j++) {
        xg_buf[j] = xg_ptr[(size_t)j * PROJW];
        xi_buf[j] = isf ? xi_ptr[(size_t)j * STATE] : 0.0f;
    }

    const ulonglong2* hp  = (const ulonglong2*)h_sh;
    const ulonglong2* hrp = (const ulonglong2*)hr_sh;

    for (int t0 = 0; t0 < SEQ; t0 += 4) {
#pragma unroll
        for (int j = 0; j < 4; j++) {
            const int t = t0 + j;
            const float xg  = xg_buf[j];
            const float xiv = xi_buf[j];
            int tp = t + 4; if (tp > SEQ - 1) tp = SEQ - 1;
            xg_buf[j] = xg_ptr[(size_t)tp * PROJW];
            if (isf) xi_buf[j] = xi_ptr[(size_t)tp * STATE];

            unsigned long long a0 = 0ull, a1 = 0ull, a2 = 0ull, a3 = 0ull;
#pragma unroll
            for (int i = 0; i < 8; i++) {
                ulonglong2 p0 = hp[2 * i];
                ulonglong2 p1 = hp[2 * i + 1];
                fma2(a0, p0.x, wg[4 * i + 0]);
                fma2(a1, p0.y, wg[4 * i + 1]);
                fma2(a2, p1.x, wg[4 * i + 2]);
                fma2(a3, p1.y, wg[4 * i + 3]);
            }
            const float gate =
                fsigmoid(hadd2(add2(add2(a0, a1), add2(a2, a3))) + xg);
            const float hk = h_sh[k];
            if (!isf) hr_sh[k] = hk * gate;
            __syncthreads();

            if (isf) {
                unsigned long long z0 = 0ull, z1 = 0ull, z2 = 0ull, z3 = 0ull;
#pragma unroll
                for (int i = 0; i < 8; i++) {
                    ulonglong2 p0 = hrp[2 * i];
                    ulonglong2 p1 = hrp[2 * i + 1];
                    fma2(z0, p0.x, wz[4 * i + 0]);
                    fma2(z1, p0.y, wz[4 * i + 1]);
                    fma2(z2, p1.x, wz[4 * i + 2]);
                    fma2(z3, p1.y, wz[4 * i + 3]);
                }
                const float z =
                    ftanh(hadd2(add2(add2(z0, z1), add2(z2, z3))) + xiv);
                const float hn = gate * hk + (1.0f - gate) * z;
                h_sh[k] = hn;
                y_ptr[(size_t)t * STATE] = hn;
            }
            __syncthreads();
        }
    }
}

// ---------------------------------------------------------------------------
// Fused: blocks 0..31 -> scan; blocks 32.. -> g-column GEMM (cols 1536..2047)
// ---------------------------------------------------------------------------
__global__ void __launch_bounds__(256)
fused_scan_ggemm(const float* __restrict__ proj_in,
                 const float* __restrict__ xi_in,
                 const float* __restrict__ sw,
                 float* __restrict__ y,
                 const float* __restrict__ xt,
                 const float* __restrict__ wint,
                 float* __restrict__ proj_out)
{
    if (blockIdx.x < 32) {
        if (threadIdx.x >= 128) return;
        scan_body(proj_in, xi_in, sw, y, blockIdx.x);
    } else {
        const int idx = blockIdx.x - 32;
        const int bx = idx & 1;        // 2 n-tiles (512 cols)
        const int by = idx >> 1;       // 128 m-tiles
        gemm_body(xt + (size_t)by * BM * DMODEL,
                  wint + (size_t)(3 * STATE + bx * BN) * DMODEL,
                  proj_out + (size_t)by * BM * PROJW + 3 * STATE + bx * BN,
                  DMODEL, PROJW);
    }
}

// ---------------------------------------------------------------------------
// Depthwise causal conv (K=4) over xi (= proj[:, :512]) + SiLU -> g_xi
// ---------------------------------------------------------------------------
__global__ void conv_silu_kernel(const float* __restrict__ proj,
                                 const float* __restrict__ cw,
                                 float* __restrict__ xi)
{
    int idx = blockIdx.x * 256 + threadIdx.x;           // over ROWS*STATE
    if (idx >= ROWS * STATE) return;
    int c   = idx & (STATE - 1);
    int row = idx >> 9;
    int s   = row & (SEQ - 1);
    float acc = 0.0f;
#pragma unroll
    for (int kk = 0; kk < 4; kk++) {
        int d = kk - 3;
        if (s + d >= 0)
            acc += cw[c * 4 + kk] * proj[(size_t)(row + d) * PROJW + c];
    }
    xi[idx] = acc * fsigmoid(acc);
}

// ---------------------------------------------------------------------------
// Epilogue: v = y * silu(g); rmsnorm; * norm_w; tf32-round; k-permuted store
// (yn is consumed only as GEMM2's A operand).
// ---------------------------------------------------------------------------
__global__ void __launch_bounds__(128)
epilogue_kernel(const float* __restrict__ y, const float* __restrict__ proj,
                const float* __restrict__ norm_w, float* __restrict__ yn)
{
    const int row = blockIdx.x;
    const int tid = threadIdx.x;
    const float* yr = y    + (size_t)row * STATE;
    const float* gr = proj + (size_t)row * PROJW + 3 * STATE;

    float v[4];
    float ss = 0.0f;
#pragma unroll
    for (int q = 0; q < 4; q++) {
        int c = tid + q * 128;
        float g = gr[c];
        float val = yr[c] * g * fsigmoid(g);
        v[q] = val;
        ss += val * val;
    }
#pragma unroll
    for (int off = 16; off > 0; off >>= 1)
        ss += __shfl_xor_sync(0xffffffffu, ss, off);
    __shared__ float red[4];
    if ((tid & 31) == 0) red[tid >> 5] = ss;
    __syncthreads();
    float tot = red[0] + red[1] + red[2] + red[3];
    float scale = rsqrtf(tot * (1.0f / 512.0f) + 1e-6f);
#pragma unroll
    for (int q = 0; q < 4; q++) {
        int c = tid + q * 128;
        int p = (c & ~7) | ((c & 3) << 1) | ((c >> 2) & 1);   // k-permute
        yn[(size_t)row * STATE + p] =
            __uint_as_float(f2tf(v[q] * scale * norm_w[c]));
    }
}

// ---------------------------------------------------------------------------
// Launch
// ---------------------------------------------------------------------------
extern "C" void kernel_launch(void* const* d_in, const int* in_sizes, int n_in,
                              void* d_out, int out_size)
{
    const float* x      = (const float*)d_in[0];
    const float* w_in   = (const float*)d_in[1];
    const float* conv_w = (const float*)d_in[2];
    const float* sw     = (const float*)d_in[3];
    const float* norm_w = (const float*)d_in[4];
    const float* w_out  = (const float*)d_in[5];
    float* out = (float*)d_out;

    float *proj, *xi, *y, *yn, *xt, *wint, *woutt;
    cudaGetSymbolAddress((void**)&proj,  g_proj);
    cudaGetSymbolAddress((void**)&xi,    g_xi);
    cudaGetSymbolAddress((void**)&y,     g_y);
    cudaGetSymbolAddress((void**)&yn,    g_yn);
    cudaGetSymbolAddress((void**)&xt,    g_xt);
    cudaGetSymbolAddress((void**)&wint,  g_wint);
    cudaGetSymbolAddress((void**)&woutt, g_woutt);

    cudaFuncSetAttribute(tf32_gemm_nt,
                         cudaFuncAttributeMaxDynamicSharedMemorySize,
                         SMEM_DYN_BYTES);
    cudaFuncSetAttribute(fused_scan_ggemm,
                         cudaFuncAttributeMaxDynamicSharedMemorySize,
                         SMEM_DYN_BYTES);

    // 0. tf32-round + k-permute inputs
    round_permute<<<(ROWS * DMODEL / 8 + 255) / 256, 256>>>(
        x, xt, ROWS * DMODEL / 8);
    round_permute<<<(PROJW * DMODEL / 8 + 255) / 256, 256>>>(
        w_in, wint, PROJW * DMODEL / 8);
    round_permute<<<(DMODEL * STATE / 8 + 255) / 256, 256>>>(
        w_out, woutt, DMODEL * STATE / 8);

    // 1. proj[:, 0:1536] = x @ w_in[0:1536]^T  (xi_raw | xf | xr)
    {
        dim3 grid(6, ROWS / BM);   // 6 n-tiles of 256 = 1536 cols
        tf32_gemm_nt<<<grid, 256, SMEM_DYN_BYTES>>>(xt, wint, proj,
                                                    DMODEL, PROJW);
    }
    // 2. depthwise conv + silu -> xi
    conv_silu_kernel<<<(ROWS * STATE) / 256, 256>>>(proj, conv_w, xi);
    // 3. fused: sequential recurrence (32 blocks) + g-column GEMM (256 blocks)
    fused_scan_ggemm<<<32 + 2 * (ROWS / BM), 256, SMEM_DYN_BYTES>>>(
        proj, xi, sw, y, xt, wint, proj);
    // 4. gate + rmsnorm -> yn (tf32-rounded, k-permuted)
    epilogue_kernel<<<ROWS, 128>>>(y, proj, norm_w, yn);
    // 5. out = yn @ w_out^T  (16384 x 1024 x 512)
    {
        dim3 grid(DMODEL / BN, ROWS / BM);  // 4 x 128
        tf32_gemm_nt<<<grid, 256, SMEM_DYN_BYTES>>>(yn, woutt, out,
                                                    STATE, DMODEL);
    }
}

// round 6
// speedup vs baseline: 1.1384x; 1.1384x over previous
#include <cuda_runtime.h>
#include <cuda_fp16.h>
#include <cuda_bf16.h>
#include <cstdint>

// ---------------------------------------------------------------------------
// Problem constants
// ---------------------------------------------------------------------------
#define BATCH   4
#define SEQ     4096
#define DMODEL  1024
#define NHEADS  8
#define HDIM    64
#define STATE   512            // NHEADS*HDIM
#define PROJW   2048           // 4*STATE
#define ROWS    (BATCH*SEQ)    // 16384

// GEMM tiling: block 128x256, 8 warps of 64x64, fp16 HMMA m16n8k16
#define BM 128
#define BN 256
#define NSTAGE 5
#define ROWB 48                         // padded smem row stride (bytes)
#define A_STAGE_B (BM * ROWB)           // 6144 B
#define B_STAGE_B (BN * ROWB)           // 12288 B
#define SMEM_DYN_BYTES (NSTAGE * (A_STAGE_B + B_STAGE_B))   // 92160 B

// ---------------------------------------------------------------------------
// Scratch (device globals -- no runtime allocation allowed)
// ---------------------------------------------------------------------------
__device__ float  g_proj[(size_t)ROWS * PROJW];   // [xi_raw | xf | xr | g]
__device__ float  g_xi  [(size_t)ROWS * STATE];   // conv+silu output
__device__ float  g_y   [(size_t)ROWS * STATE];   // recurrence output
__device__ __half g_xh  [(size_t)ROWS * DMODEL];  // x (fp16)
__device__ __half g_winh[(size_t)PROJW * DMODEL]; // w_in (fp16)
__device__ __half g_wouth[(size_t)DMODEL * STATE];// w_out (fp16)
__device__ __half g_ynh [(size_t)ROWS * STATE];   // gated+normed (fp16)

// ---------------------------------------------------------------------------
// Helpers (scan)
// ---------------------------------------------------------------------------
__device__ __forceinline__ unsigned long long pk2(float lo, float hi) {
    unsigned long long r;
    asm("mov.b64 %0, {%1, %2};" : "=l"(r) : "f"(lo), "f"(hi));
    return r;
}
__device__ __forceinline__ void fma2(unsigned long long& d,
                                     unsigned long long a,
                                     unsigned long long b) {
    asm("fma.rn.f32x2 %0, %1, %2, %0;" : "+l"(d) : "l"(a), "l"(b));
}
__device__ __forceinline__ unsigned long long add2(unsigned long long a,
                                                   unsigned long long b) {
    unsigned long long d;
    asm("add.rn.f32x2 %0, %1, %2;" : "=l"(d) : "l"(a), "l"(b));
    return d;
}
__device__ __forceinline__ float hadd2(unsigned long long v) {
    float a, b;
    asm("mov.b64 {%0, %1}, %2;" : "=f"(a), "=f"(b) : "l"(v));
    return a + b;
}
__device__ __forceinline__ float fsigmoid(float x) {
    return __fdividef(1.0f, 1.0f + __expf(-x));
}
__device__ __forceinline__ float ftanh(float x) {
    float e = __expf(2.0f * x);
    return 1.0f - __fdividef(2.0f, e + 1.0f);
}

// ---------------------------------------------------------------------------
// GEMM primitives
// ---------------------------------------------------------------------------
__device__ __forceinline__ void mma_f16(float* c, const uint32_t* a,
                                        uint32_t b0, uint32_t b1) {
    asm volatile(
        "mma.sync.aligned.m16n8k16.row.col.f32.f16.f16.f32 "
        "{%0,%1,%2,%3}, {%4,%5,%6,%7}, {%8,%9}, {%0,%1,%2,%3};\n"
        : "+f"(c[0]), "+f"(c[1]), "+f"(c[2]), "+f"(c[3])
        : "r"(a[0]), "r"(a[1]), "r"(a[2]), "r"(a[3]), "r"(b0), "r"(b1));
}
__device__ __forceinline__ void ldsm4(uint32_t& r0, uint32_t& r1,
                                      uint32_t& r2, uint32_t& r3,
                                      uint32_t addr) {
    asm volatile("ldmatrix.sync.aligned.m8n8.x4.shared.b16 "
                 "{%0,%1,%2,%3}, [%4];"
                 : "=r"(r0), "=r"(r1), "=r"(r2), "=r"(r3) : "r"(addr));
}
__device__ __forceinline__ void cp16(uint32_t dst, const void* src) {
    asm volatile("cp.async.cg.shared.global [%0], [%1], 16;\n"
                 :: "r"(dst), "l"(src));
}

// ---------------------------------------------------------------------------
// Pre-pass: fp32 -> fp16 (rn), 8 elems/thread
// ---------------------------------------------------------------------------
__global__ void __launch_bounds__(256)
f32_to_f16_kernel(const float* __restrict__ src, __half* __restrict__ dst,
                  int n8)
{
    int g = blockIdx.x * 256 + threadIdx.x;
    if (g >= n8) return;
    const float4* s = (const float4*)(src + (size_t)g * 8);
    float4 a = s[0], b = s[1];
    __half2 h0 = __floats2half2_rn(a.x, a.y);
    __half2 h1 = __floats2half2_rn(a.z, a.w);
    __half2 h2 = __floats2half2_rn(b.x, b.y);
    __half2 h3 = __floats2half2_rn(b.z, b.w);
    uint4 o;
    o.x = *(uint32_t*)&h0; o.y = *(uint32_t*)&h1;
    o.z = *(uint32_t*)&h2; o.w = *(uint32_t*)&h3;
    *(uint4*)(dst + (size_t)g * 8) = o;
}

// ---------------------------------------------------------------------------
// 128x256 fp16 GEMM body (NT): C[m,n] = sum_k A[m,k]*B[n,k], fp32 accum/out.
// 256 threads, 8 warps of 64x64, cp.async 5-stage, ldmatrix fragments.
// K % 16 == 0, K >= 64.
// ---------------------------------------------------------------------------
__device__ __forceinline__ void gemm_body(const __half* __restrict__ Ag0,
                                          const __half* __restrict__ Bg0,
                                          float* __restrict__ Cg0,
                                          int K, int ldc)
{
    extern __shared__ char smem_dyn[];
    char* Asm = smem_dyn;
    char* Bsm = smem_dyn + NSTAGE * A_STAGE_B;
    const uint32_t aBase = (uint32_t)__cvta_generic_to_shared(Asm);
    const uint32_t bBase = (uint32_t)__cvta_generic_to_shared(Bsm);

    const int tid   = threadIdx.x;
    const int lane  = tid & 31;
    const int warp  = tid >> 5;
    const int group = lane >> 2;
    const int tig   = lane & 3;
    const int wm = (warp >> 2) * 64;   // 2 warp rows
    const int wn = (warp & 3) * 64;    // 4 warp cols

    // ldmatrix per-lane offset within a 16x16 tile (rows at ROWB stride)
    const int lj = lane >> 3;          // matrix id 0..3
    const int lrr = lane & 7;
    const uint32_t fragOff =
        (uint32_t)(((lj & 1) * 8 + lrr) * ROWB + (lj >> 1) * 16);

    float c[4][8][4];
#pragma unroll
    for (int mt = 0; mt < 4; mt++)
#pragma unroll
        for (int nt = 0; nt < 8; nt++)
#pragma unroll
            for (int q = 0; q < 4; q++) c[mt][nt][q] = 0.0f;

    // cp.async mapping: 16B chunks (8 halves); row k16 = 32B = 2 chunks
    const int arow  = tid >> 1;
    const int ahalf = tid & 1;
    const uint32_t aOff  = (uint32_t)(arow * ROWB + ahalf * 16);
    const uint32_t bOff0 = aOff;
    const uint32_t bOff1 = (uint32_t)((arow + 128) * ROWB + ahalf * 16);
    const int niter = K >> 4;

    auto load_stage = [&](int st, int ko) {
        const uint32_t aS = aBase + (uint32_t)(st * A_STAGE_B);
        const uint32_t bS = bBase + (uint32_t)(st * B_STAGE_B);
        cp16(aS + aOff,  Ag0 + (size_t)arow * K + ko + ahalf * 8);
        cp16(bS + bOff0, Bg0 + (size_t)arow * K + ko + ahalf * 8);
        cp16(bS + bOff1, Bg0 + (size_t)(arow + 128) * K + ko + ahalf * 8);
        asm volatile("cp.async.commit_group;\n");
    };

    load_stage(0, 0);
    load_stage(1, 16);
    load_stage(2, 32);
    load_stage(3, 48);

    int st = 0, ldst = 4;
    for (int it = 0; it < niter; it++) {
        asm volatile("cp.async.wait_group 3;\n");
        __syncthreads();

        const uint32_t aT = aBase + (uint32_t)(st * A_STAGE_B);
        const uint32_t bT = bBase + (uint32_t)(st * B_STAGE_B);

        uint32_t a[4][4], bf[4][4];
#pragma unroll
        for (int mt = 0; mt < 4; mt++)
            ldsm4(a[mt][0], a[mt][1], a[mt][2], a[mt][3],
                  aT + (uint32_t)((wm + mt * 16) * ROWB) + fragOff);
#pragma unroll
        for (int bt = 0; bt < 4; bt++)
            ldsm4(bf[bt][0], bf[bt][1], bf[bt][2], bf[bt][3],
                  bT + (uint32_t)((wn + bt * 16) * ROWB) + fragOff);

#pragma unroll
        for (int mt = 0; mt < 4; mt++)
#pragma unroll
            for (int nt = 0; nt < 8; nt++) {
                const int bt = nt >> 1, s = nt & 1;
                mma_f16(c[mt][nt], a[mt], bf[bt][s], bf[bt][s + 2]);
            }

        if (it + 4 < niter)
            load_stage(ldst, (it + 4) * 16);
        else
            asm volatile("cp.async.commit_group;\n");  // uniform group count

        st   = (st   + 1 == NSTAGE) ? 0 : st + 1;
        ldst = (ldst + 1 == NSTAGE) ? 0 : ldst + 1;
    }

#pragma unroll
    for (int mt = 0; mt < 4; mt++) {
        const int m0 = wm + mt * 16 + group;
#pragma unroll
        for (int nt = 0; nt < 8; nt++) {
            const int n0 = wn + nt * 8 + 2 * tig;
            *(float2*)(Cg0 + (size_t)m0 * ldc + n0) =
                make_float2(c[mt][nt][0], c[mt][nt][1]);
            *(float2*)(Cg0 + (size_t)(m0 + 8) * ldc + n0) =
                make_float2(c[mt][nt][2], c[mt][nt][3]);
        }
    }
}

__global__ void __launch_bounds__(256)
f16_gemm_nt(const __half* __restrict__ A, const __half* __restrict__ B,
            float* __restrict__ C, int K, int ldc)
{
    gemm_body(A + (size_t)blockIdx.y * BM * K,
              B + (size_t)blockIdx.x * BN * K,
              C + (size_t)blockIdx.y * BM * ldc + blockIdx.x * BN,
              K, ldc);
}

// ---------------------------------------------------------------------------
// Sequential recurrence body: 128 threads, one (b,head) per bh.
// ---------------------------------------------------------------------------
__device__ void scan_body(const float* __restrict__ proj,
                          const float* __restrict__ xi_in,
                          const float* __restrict__ sw,
                          float* __restrict__ y, int bh)
{
    const int tid  = threadIdx.x;
    const int k    = tid & 63;
    const bool isf = tid < 64;
    const int head = bh & 7;
    const int b    = bh >> 3;

    __shared__ __align__(16) float h_sh[64];
    __shared__ __align__(16) float hr_sh[64];

    unsigned long long wg[32];  // Wf (f-threads) or Wr (r-threads)
    unsigned long long wz[32];  // W  (f-threads only)
    {
        const int gidx = isf ? (NHEADS + head) : (2 * NHEADS + head);
        const float* base = sw + (size_t)gidx * 64 * 64 + k;
#pragma unroll
        for (int i = 0; i < 32; i++)
            wg[i] = pk2(base[(2 * i) * 64], base[(2 * i + 1) * 64]);
        if (isf) {
            const float* bz = sw + (size_t)head * 64 * 64 + k;
#pragma unroll
            for (int i = 0; i < 32; i++)
                wz[i] = pk2(bz[(2 * i) * 64], bz[(2 * i + 1) * 64]);
        }
    }

    if (tid < 64) h_sh[tid] = 0.0f;
    __syncthreads();

    const float* xg_ptr = proj + (size_t)b * SEQ * PROJW
                          + (isf ? STATE : 2 * STATE) + head * HDIM + k;
    const float* xi_ptr = xi_in + (size_t)b * SEQ * STATE + head * HDIM + k;
    float* y_ptr = y + (size_t)b * SEQ * STATE + head * HDIM + k;

    float xg_buf[4], xi_buf[4];
#pragma unroll
    for (int j = 0; j < 4; j++) {
        xg_buf[j] = xg_ptr[(size_t)j * PROJW];
        xi_buf[j] = isf ? xi_ptr[(size_t)j * STATE] : 0.0f;
    }

    const ulonglong2* hp  = (const ulonglong2*)h_sh;
    const ulonglong2* hrp = (const ulonglong2*)hr_sh;

    for (int t0 = 0; t0 < SEQ; t0 += 4) {
#pragma unroll
        for (int j = 0; j < 4; j++) {
            const int t = t0 + j;
            const float xg  = xg_buf[j];
            const float xiv = xi_buf[j];
            int tp = t + 4; if (tp > SEQ - 1) tp = SEQ - 1;
            xg_buf[j] = xg_ptr[(size_t)tp * PROJW];
            if (isf) xi_buf[j] = xi_ptr[(size_t)tp * STATE];

            unsigned long long a0 = 0ull, a1 = 0ull, a2 = 0ull, a3 = 0ull;
#pragma unroll
            for (int i = 0; i < 8; i++) {
                ulonglong2 p0 = hp[2 * i];
                ulonglong2 p1 = hp[2 * i + 1];
                fma2(a0, p0.x, wg[4 * i + 0]);
                fma2(a1, p0.y, wg[4 * i + 1]);
                fma2(a2, p1.x, wg[4 * i + 2]);
                fma2(a3, p1.y, wg[4 * i + 3]);
            }
            const float gate =
                fsigmoid(hadd2(add2(add2(a0, a1), add2(a2, a3))) + xg);
            const float hk = h_sh[k];
            if (!isf) hr_sh[k] = hk * gate;
            __syncthreads();

            if (isf) {
                unsigned long long z0 = 0ull, z1 = 0ull, z2 = 0ull, z3 = 0ull;
#pragma unroll
                for (int i = 0; i < 8; i++) {
                    ulonglong2 p0 = hrp[2 * i];
                    ulonglong2 p1 = hrp[2 * i + 1];
                    fma2(z0, p0.x, wz[4 * i + 0]);
                    fma2(z1, p0.y, wz[4 * i + 1]);
                    fma2(z2, p1.x, wz[4 * i + 2]);
                    fma2(z3, p1.y, wz[4 * i + 3]);
                }
                const float z =
                    ftanh(hadd2(add2(add2(z0, z1), add2(z2, z3))) + xiv);
                const float hn = gate * hk + (1.0f - gate) * z;
                h_sh[k] = hn;
                y_ptr[(size_t)t * STATE] = hn;
            }
            __syncthreads();
        }
    }
}

// ---------------------------------------------------------------------------
// Fused: blocks 0..31 -> scan; blocks 32.. -> g-column GEMM (cols 1536..2047)
// ---------------------------------------------------------------------------
__global__ void __launch_bounds__(256)
fused_scan_ggemm(const float* __restrict__ proj_in,
                 const float* __restrict__ xi_in,
                 const float* __restrict__ sw,
                 float* __restrict__ y,
                 const __half* __restrict__ xh,
                 const __half* __restrict__ winh,
                 float* __restrict__ proj_out)
{
    if (blockIdx.x < 32) {
        if (threadIdx.x >= 128) return;
        scan_body(proj_in, xi_in, sw, y, blockIdx.x);
    } else {
        const int idx = blockIdx.x - 32;
        const int bx = idx & 1;        // 2 n-tiles (512 cols)
        const int by = idx >> 1;       // 128 m-tiles
        gemm_body(xh + (size_t)by * BM * DMODEL,
                  winh + (size_t)(3 * STATE + bx * BN) * DMODEL,
                  proj_out + (size_t)by * BM * PROJW + 3 * STATE + bx * BN,
                  DMODEL, PROJW);
    }
}

// ---------------------------------------------------------------------------
// Depthwise causal conv (K=4) over xi (= proj[:, :512]) + SiLU -> g_xi
// ---------------------------------------------------------------------------
__global__ void conv_silu_kernel(const float* __restrict__ proj,
                                 const float* __restrict__ cw,
                                 float* __restrict__ xi)
{
    int idx = blockIdx.x * 256 + threadIdx.x;           // over ROWS*STATE
    if (idx >= ROWS * STATE) return;
    int c   = idx & (STATE - 1);
    int row = idx >> 9;
    int s   = row & (SEQ - 1);
    float acc = 0.0f;
#pragma unroll
    for (int kk = 0; kk < 4; kk++) {
        int d = kk - 3;
        if (s + d >= 0)
            acc += cw[c * 4 + kk] * proj[(size_t)(row + d) * PROJW + c];
    }
    xi[idx] = acc * fsigmoid(acc);
}

// ---------------------------------------------------------------------------
// Epilogue: v = y * silu(g); rmsnorm; * norm_w; -> fp16 yn (GEMM2's A)
// ---------------------------------------------------------------------------
__global__ void __launch_bounds__(128)
epilogue_kernel(const float* __restrict__ y, const float* __restrict__ proj,
                const float* __restrict__ norm_w, __half* __restrict__ yn)
{
    const int row = blockIdx.x;
    const int tid = threadIdx.x;
    const float* yr = y    + (size_t)row * STATE;
    const float* gr = proj + (size_t)row * PROJW + 3 * STATE;

    float v[4];
    float ss = 0.0f;
#pragma unroll
    for (int q = 0; q < 4; q++) {
        int c = tid + q * 128;
        float g = gr[c];
        float val = yr[c] * g * fsigmoid(g);
        v[q] = val;
        ss += val * val;
    }
#pragma unroll
    for (int off = 16; off > 0; off >>= 1)
        ss += __shfl_xor_sync(0xffffffffu, ss, off);
    __shared__ float red[4];
    if ((tid & 31) == 0) red[tid >> 5] = ss;
    __syncthreads();
    float tot = red[0] + red[1] + red[2] + red[3];
    float scale = rsqrtf(tot * (1.0f / 512.0f) + 1e-6f);
#pragma unroll
    for (int q = 0; q < 4; q++) {
        int c = tid + q * 128;
        yn[(size_t)row * STATE + c] = __float2half_rn(v[q] * scale * norm_w[c]);
    }
}

// ---------------------------------------------------------------------------
// Launch
// ---------------------------------------------------------------------------
extern "C" void kernel_launch(void* const* d_in, const int* in_sizes, int n_in,
                              void* d_out, int out_size)
{
    const float* x      = (const float*)d_in[0];
    const float* w_in   = (const float*)d_in[1];
    const float* conv_w = (const float*)d_in[2];
    const float* sw     = (const float*)d_in[3];
    const float* norm_w = (const float*)d_in[4];
    const float* w_out  = (const float*)d_in[5];
    float* out = (float*)d_out;

    float *proj, *xi, *y;
    __half *xh, *winh, *wouth, *ynh;
    cudaGetSymbolAddress((void**)&proj,  g_proj);
    cudaGetSymbolAddress((void**)&xi,    g_xi);
    cudaGetSymbolAddress((void**)&y,     g_y);
    cudaGetSymbolAddress((void**)&xh,    g_xh);
    cudaGetSymbolAddress((void**)&winh,  g_winh);
    cudaGetSymbolAddress((void**)&wouth, g_wouth);
    cudaGetSymbolAddress((void**)&ynh,   g_ynh);

    cudaFuncSetAttribute(f16_gemm_nt,
                         cudaFuncAttributeMaxDynamicSharedMemorySize,
                         SMEM_DYN_BYTES);
    cudaFuncSetAttribute(fused_scan_ggemm,
                         cudaFuncAttributeMaxDynamicSharedMemorySize,
                         SMEM_DYN_BYTES);

    // 0. fp32 -> fp16 conversions
    f32_to_f16_kernel<<<(ROWS * DMODEL / 8 + 255) / 256, 256>>>(
        x, xh, ROWS * DMODEL / 8);
    f32_to_f16_kernel<<<(PROJW * DMODEL / 8 + 255) / 256, 256>>>(
        w_in, winh, PROJW * DMODEL / 8);
    f32_to_f16_kernel<<<(DMODEL * STATE / 8 + 255) / 256, 256>>>(
        w_out, wouth, DMODEL * STATE / 8);

    // 1. proj[:, 0:1536] = x @ w_in[0:1536]^T  (xi_raw | xf | xr)
    {
        dim3 grid(6, ROWS / BM);   // 6 n-tiles of 256 = 1536 cols
        f16_gemm_nt<<<grid, 256, SMEM_DYN_BYTES>>>(xh, winh, proj,
                                                   DMODEL, PROJW);
    }
    // 2. depthwise conv + silu -> xi
    conv_silu_kernel<<<(ROWS * STATE) / 256, 256>>>(proj, conv_w, xi);
    // 3. fused: sequential recurrence (32 blocks) + g-column GEMM (256 blocks)
    fused_scan_ggemm<<<32 + 2 * (ROWS / BM), 256, SMEM_DYN_BYTES>>>(
        proj, xi, sw, y, xh, winh, proj);
    // 4. gate + rmsnorm -> ynh (fp16)
    epilogue_kernel<<<ROWS, 128>>>(y, proj, norm_w, ynh);
    // 5. out = yn @ w_out^T  (16384 x 1024 x 512)
    {
        dim3 grid(DMODEL / BN, ROWS / BM);  // 4 x 128
        f16_gemm_nt<<<grid, 256, SMEM_DYN_BYTES>>>(ynh, wouth, out,
                                                   STATE, DMODEL);
    }
}